// round 12
// baseline (speedup 1.0000x reference)
#include <cuda_runtime.h>
#include <cuda_bf16.h>
#include <math.h>

#define NMAX   100352          // >= 100000, padded
#define EMAX   1300000
#define DIM    64
#define SCAN_B 1024
#define NBLK   128             // >= ceil(NMAX/SCAN_B)

// ---------------- device scratch ----------------
__device__ int   g_deg[NMAX];
__device__ int   g_off[NMAX];                 // scan -> start; after fill -> end
__device__ unsigned long long g_state[NBLK];  // lookback: flag<<32 | value
__device__ float g_dinv[NMAX];
__device__ int   g_col[EMAX];
__device__ int   g_is64;                      // 1 if edge_index is int64
__device__ __align__(256) float g_h[(size_t)NMAX * DIM];
__device__ __align__(256) float g_agg[(size_t)NMAX * DIM];

// ---------------- init: zero counters/state + dtype detection ----------------
__global__ void init_all(const unsigned int* __restrict__ w, int n) {
    int i = blockIdx.x * blockDim.x + threadIdx.x;
    if (i < n) g_deg[i] = 0;
    if (i < NBLK) g_state[i] = 0ULL;

    if (blockIdx.x == 0) {
        __shared__ unsigned int acc[256];
        unsigned int v = 0;
        for (int t = threadIdx.x; t < 1024; t += 256) v |= w[2 * t + 1];
        acc[threadIdx.x] = v;
        __syncthreads();
        for (int s = 128; s > 0; s >>= 1) {
            if (threadIdx.x < s) acc[threadIdx.x] |= acc[threadIdx.x + s];
            __syncthreads();
        }
        if (threadIdx.x == 0) g_is64 = (acc[0] == 0) ? 1 : 0;
    }
}

__device__ __forceinline__ int load_idx(const void* ei, long long pos) {
    if (g_is64) return (int)((const long long*)ei)[pos];
    return ((const int*)ei)[pos];
}

// ---------------- CSR build ----------------
__global__ void count_deg(const void* __restrict__ ei, int E, int n) {
    int e = blockIdx.x * blockDim.x + threadIdx.x;
    if (e < E) {
        int d = load_idx(ei, (long long)E + e);
        if ((unsigned)d < (unsigned)n) atomicAdd(&g_deg[d], 1);
    }
}

// Single-pass scan with decoupled lookback. Produces g_off (exclusive) + g_dinv.
__global__ __launch_bounds__(SCAN_B) void scan_lookback(int n) {
    __shared__ int warpsum[32];
    __shared__ int s_total;
    __shared__ int s_excl;

    int bid  = blockIdx.x;
    int tid  = threadIdx.x;
    int lane = tid & 31;
    int w    = tid >> 5;
    int i    = bid * SCAN_B + tid;

    int v = (i < n) ? g_deg[i] : 0;
    if (i < n) g_dinv[i] = rsqrtf((float)(v + 1));   // +1 self loop

    int x = v;
    #pragma unroll
    for (int s = 1; s < 32; s <<= 1) {
        int t = __shfl_up_sync(0xffffffffu, x, s);
        if (lane >= s) x += t;
    }
    if (lane == 31) warpsum[w] = x;
    __syncthreads();
    if (w == 0) {
        int y = warpsum[lane];
        int yi = y;
        #pragma unroll
        for (int s = 1; s < 32; s <<= 1) {
            int t = __shfl_up_sync(0xffffffffu, yi, s);
            if (lane >= s) yi += t;
        }
        warpsum[lane] = yi - y;
    }
    __syncthreads();
    int incl = x + warpsum[w];

    if (tid == SCAN_B - 1) {
        s_total = incl;
        unsigned long long flag = (bid == 0) ? 2ULL : 1ULL;
        atomicExch(&g_state[bid], (flag << 32) | (unsigned int)incl);
    }
    __syncthreads();

    if (bid == 0) {
        if (tid == 0) s_excl = 0;
    } else if (w == 0) {
        int excl = 0;
        int idx = bid - 1;
        for (;;) {
            int look = idx - lane;
            int flag, val;
            if (look >= 0) {
                unsigned long long s;
                do { s = atomicAdd(&g_state[look], 0ULL); flag = (int)(s >> 32); } while (flag == 0);
                val = (int)(unsigned int)s;
            } else { flag = 2; val = 0; }
            unsigned int pm = __ballot_sync(0xffffffffu, flag == 2);
            int L = pm ? (__ffs(pm) - 1) : 31;
            int contrib = (lane <= L) ? val : 0;
            #pragma unroll
            for (int o = 16; o > 0; o >>= 1) contrib += __shfl_down_sync(0xffffffffu, contrib, o);
            contrib = __shfl_sync(0xffffffffu, contrib, 0);
            excl += contrib;
            if (pm) break;
            idx -= 32;
        }
        if (lane == 0) {
            s_excl = excl;
            atomicExch(&g_state[bid], (2ULL << 32) | (unsigned int)(excl + s_total));
        }
    }
    __syncthreads();

    if (i < n) g_off[i] = incl - v + s_excl;
}

// fill uses g_off itself as the cursor (post: g_off[i] = end offset)
__global__ void fill_csr(const void* __restrict__ ei, int E, int n) {
    int e = blockIdx.x * blockDim.x + threadIdx.x;
    if (e < E) {
        int d = load_idx(ei, (long long)E + e);
        int s = load_idx(ei, e);
        if ((unsigned)d < (unsigned)n) {
            int p = atomicAdd(&g_off[d], 1);
            g_col[p] = ((unsigned)s < (unsigned)n) ? s : d;
        }
    }
}

// ---------------- packed fp32 helpers ----------------
__device__ __forceinline__ unsigned long long pack_dup(float x) {
    unsigned long long r;
    asm("mov.b64 %0, {%1, %1};" : "=l"(r) : "f"(x));
    return r;
}
__device__ __forceinline__ void ffma2(unsigned long long& d,
                                      unsigned long long a, unsigned long long b) {
    asm("fma.rn.f32x2 %0, %1, %2, %0;" : "+l"(d) : "l"(a), "l"(b));
}
__device__ __forceinline__ float2 unpack2(unsigned long long v) {
    float2 r;
    asm("mov.b64 {%0, %1}, %2;" : "=f"(r.x), "=f"(r.y) : "l"(v));
    return r;
}

// ---------------- GEMM: Y = op(X) @ W, f32x2 row-pair accumulators ----------------
// 64x64 tile, 256 threads, each thread: 4 rows (2 f32x2 pairs) x 4 cols.
template<int PRE_RELU>
__global__ __launch_bounds__(256) void gemm64(
    const float* __restrict__ X, const float* __restrict__ W,
    const float* __restrict__ scale,     // per-row, may be null
    const float* __restrict__ postBias,  // per-col, may be null
    float* __restrict__ Y, int n)
{
    __shared__ float Xt[64][66];   // Xt[k][r]  (transposed X tile)
    __shared__ float Ws[64][68];   // Ws[k][c]
    int tid  = threadIdx.x;
    int row0 = blockIdx.x * 64;

    #pragma unroll 4
    for (int t = tid; t < 64 * 64; t += 256) {
        int r = t >> 6, c = t & 63;
        Ws[r][c] = W[t];
        int gr = row0 + r;
        float v = (gr < n) ? X[(size_t)gr * 64 + c] : 0.f;
        if (PRE_RELU) v = fmaxf(v, 0.f);
        Xt[c][r] = v;
    }
    __syncthreads();

    int ty = tid >> 4, tx = tid & 15;
    int r0 = ty * 4,  c0 = tx * 4;

    unsigned long long acc[2][4] = {};   // [row-pair][col]

    #pragma unroll
    for (int k = 0; k < 64; k++) {
        unsigned long long xa = *(const unsigned long long*)&Xt[k][r0];      // rows r0,r0+1
        unsigned long long xb = *(const unsigned long long*)&Xt[k][r0 + 2];  // rows r0+2,r0+3
        float4 wv = *(const float4*)&Ws[k][c0];
        unsigned long long w0 = pack_dup(wv.x);
        unsigned long long w1 = pack_dup(wv.y);
        unsigned long long w2 = pack_dup(wv.z);
        unsigned long long w3 = pack_dup(wv.w);
        ffma2(acc[0][0], xa, w0); ffma2(acc[0][1], xa, w1);
        ffma2(acc[0][2], xa, w2); ffma2(acc[0][3], xa, w3);
        ffma2(acc[1][0], xb, w0); ffma2(acc[1][1], xb, w1);
        ffma2(acc[1][2], xb, w2); ffma2(acc[1][3], xb, w3);
    }

    float4 bv = make_float4(0.f, 0.f, 0.f, 0.f);
    if (postBias) bv = *(const float4*)&postBias[c0];

    #pragma unroll
    for (int i = 0; i < 4; i++) {
        int gr = row0 + r0 + i;
        if (gr < n) {
            float s = scale ? scale[gr] : 1.f;
            int p = i >> 1, q = i & 1;
            float2 a0 = unpack2(acc[p][0]);
            float2 a1 = unpack2(acc[p][1]);
            float2 a2 = unpack2(acc[p][2]);
            float2 a3 = unpack2(acc[p][3]);
            float4 o;
            o.x = (q ? a0.y : a0.x) * s + bv.x;
            o.y = (q ? a1.y : a1.x) * s + bv.y;
            o.z = (q ? a2.y : a2.x) * s + bv.z;
            o.w = (q ? a3.y : a3.x) * s + bv.w;
            *(float4*)&Y[(size_t)gr * 64 + c0] = o;
        }
    }
}

// ---------------- Gather aggregation: one warp per node, float2 lanes ----------------
// out[i] = dinv[i] * ( H[i] + sum_{e: dst=i} H[src_e] ) + bias
__global__ __launch_bounds__(256) void gather(
    const float* __restrict__ H, const float* __restrict__ bias,
    float* __restrict__ out, int n)
{
    int warp = (blockIdx.x * blockDim.x + threadIdx.x) >> 5;
    int lane = threadIdx.x & 31;
    if (warp >= n) return;

    int dg = g_deg[warp];
    int o  = g_off[warp] - dg;          // g_off holds end offsets after fill

    float2 a = *(const float2*)(H + (size_t)warp * 64 + lane * 2);   // self loop

    for (int base = 0; base < dg; base += 32) {
        int m  = min(32, dg - base);
        int sj = (lane < m) ? g_col[o + base + lane] : 0;
        #pragma unroll 4
        for (int j = 0; j < m; j++) {
            int s = __shfl_sync(0xffffffffu, sj, j);
            float2 v = *(const float2*)(H + (size_t)s * 64 + lane * 2);
            a.x += v.x;
            a.y += v.y;
        }
    }
    float di = g_dinv[warp];
    float2 bv = *(const float2*)(bias + lane * 2);
    float2 ov;
    ov.x = a.x * di + bv.x;
    ov.y = a.y * di + bv.y;
    *(float2*)(out + (size_t)warp * 64 + lane * 2) = ov;
}

// ---------------- launch ----------------
extern "C" void kernel_launch(void* const* d_in, const int* in_sizes, int n_in,
                              void* d_out, int out_size) {
    const float* x  = (const float*)d_in[0];
    const void*  ei = d_in[1];
    const float* W1 = (const float*)d_in[2];
    const float* b1 = (const float*)d_in[3];
    const float* W2 = (const float*)d_in[4];
    const float* b2 = (const float*)d_in[5];
    const float* Wl = (const float*)d_in[6];
    const float* bl = (const float*)d_in[7];
    float* out = (float*)d_out;

    int n = in_sizes[0] / DIM;          // 100000
    int E = in_sizes[1] / 2;            // 1200000

    float *h, *agg, *dinv;
    cudaGetSymbolAddress((void**)&h,    g_h);
    cudaGetSymbolAddress((void**)&agg,  g_agg);
    cudaGetSymbolAddress((void**)&dinv, g_dinv);

    int nbScan = (n + SCAN_B - 1) / SCAN_B;
    int nbE    = (E + 255) / 256;
    int nbN    = (n + 255) / 256;
    int nbG    = (n * 32 + 255) / 256;       // warp per node
    int nbM    = (n + 63) / 64;

    // CSR build
    init_all<<<nbN, 256>>>((const unsigned int*)ei, n);
    count_deg<<<nbE, 256>>>(ei, E, n);
    scan_lookback<<<nbScan, SCAN_B>>>(n);
    fill_csr<<<nbE, 256>>>(ei, E, n);

    // layer 1
    gemm64<0><<<nbM, 256>>>(x, W1, dinv, nullptr, h, n);
    gather<<<nbG, 256>>>(h, b1, agg, n);

    // layer 2
    gemm64<1><<<nbM, 256>>>(agg, W2, dinv, nullptr, h, n);
    gather<<<nbG, 256>>>(h, b2, agg, n);

    // head
    gemm64<0><<<nbM, 256>>>(agg, Wl, nullptr, bl, out, n);
}

// round 13
// speedup vs baseline: 1.0024x; 1.0024x over previous
#include <cuda_runtime.h>
#include <cuda_bf16.h>
#include <math.h>

#define NMAX   100352          // >= 100000, padded
#define EMAX   1300000
#define DIM    64
#define SCAN_B 1024
#define NBLK   128             // >= ceil(NMAX/SCAN_B)

// ---------------- device scratch ----------------
__device__ int   g_deg[NMAX];
__device__ int   g_off[NMAX];                 // scan -> start; after fill -> end
__device__ unsigned long long g_state[NBLK];  // lookback: flag<<32 | value
__device__ float g_dinv[NMAX];
__device__ int   g_col[EMAX];
__device__ int   g_is64;                      // 1 if edge_index is int64
__device__ __align__(256) float g_h[(size_t)NMAX * DIM];
__device__ __align__(256) float g_agg[(size_t)NMAX * DIM];

// ---------------- init: zero counters/state + dtype detection ----------------
__global__ void init_all(const unsigned int* __restrict__ w, int n) {
    int i = blockIdx.x * blockDim.x + threadIdx.x;
    if (i < n) g_deg[i] = 0;
    if (i < NBLK) g_state[i] = 0ULL;

    if (blockIdx.x == 0) {
        __shared__ unsigned int acc[256];
        unsigned int v = 0;
        for (int t = threadIdx.x; t < 1024; t += 256) v |= w[2 * t + 1];
        acc[threadIdx.x] = v;
        __syncthreads();
        for (int s = 128; s > 0; s >>= 1) {
            if (threadIdx.x < s) acc[threadIdx.x] |= acc[threadIdx.x + s];
            __syncthreads();
        }
        if (threadIdx.x == 0) g_is64 = (acc[0] == 0) ? 1 : 0;
    }
}

__device__ __forceinline__ int load_idx(const void* ei, long long pos) {
    if (g_is64) return (int)((const long long*)ei)[pos];
    return ((const int*)ei)[pos];
}

// ---------------- CSR build ----------------
__global__ void count_deg(const void* __restrict__ ei, int E, int n) {
    int e = blockIdx.x * blockDim.x + threadIdx.x;
    if (e < E) {
        int d = load_idx(ei, (long long)E + e);
        if ((unsigned)d < (unsigned)n) atomicAdd(&g_deg[d], 1);
    }
}

// Single-pass scan with decoupled lookback. Produces g_off (exclusive) + g_dinv.
__global__ __launch_bounds__(SCAN_B) void scan_lookback(int n) {
    __shared__ int warpsum[32];
    __shared__ int s_total;
    __shared__ int s_excl;

    int bid  = blockIdx.x;
    int tid  = threadIdx.x;
    int lane = tid & 31;
    int w    = tid >> 5;
    int i    = bid * SCAN_B + tid;

    int v = (i < n) ? g_deg[i] : 0;
    if (i < n) g_dinv[i] = rsqrtf((float)(v + 1));   // +1 self loop

    int x = v;
    #pragma unroll
    for (int s = 1; s < 32; s <<= 1) {
        int t = __shfl_up_sync(0xffffffffu, x, s);
        if (lane >= s) x += t;
    }
    if (lane == 31) warpsum[w] = x;
    __syncthreads();
    if (w == 0) {
        int y = warpsum[lane];
        int yi = y;
        #pragma unroll
        for (int s = 1; s < 32; s <<= 1) {
            int t = __shfl_up_sync(0xffffffffu, yi, s);
            if (lane >= s) yi += t;
        }
        warpsum[lane] = yi - y;
    }
    __syncthreads();
    int incl = x + warpsum[w];

    if (tid == SCAN_B - 1) {
        s_total = incl;
        unsigned long long flag = (bid == 0) ? 2ULL : 1ULL;
        atomicExch(&g_state[bid], (flag << 32) | (unsigned int)incl);
    }
    __syncthreads();

    if (bid == 0) {
        if (tid == 0) s_excl = 0;
    } else if (w == 0) {
        int excl = 0;
        int idx = bid - 1;
        for (;;) {
            int look = idx - lane;
            int flag, val;
            if (look >= 0) {
                unsigned long long s;
                do { s = atomicAdd(&g_state[look], 0ULL); flag = (int)(s >> 32); } while (flag == 0);
                val = (int)(unsigned int)s;
            } else { flag = 2; val = 0; }
            unsigned int pm = __ballot_sync(0xffffffffu, flag == 2);
            int L = pm ? (__ffs(pm) - 1) : 31;
            int contrib = (lane <= L) ? val : 0;
            #pragma unroll
            for (int o = 16; o > 0; o >>= 1) contrib += __shfl_down_sync(0xffffffffu, contrib, o);
            contrib = __shfl_sync(0xffffffffu, contrib, 0);
            excl += contrib;
            if (pm) break;
            idx -= 32;
        }
        if (lane == 0) {
            s_excl = excl;
            atomicExch(&g_state[bid], (2ULL << 32) | (unsigned int)(excl + s_total));
        }
    }
    __syncthreads();

    if (i < n) g_off[i] = incl - v + s_excl;
}

// fill uses g_off itself as the cursor (post: g_off[i] = end offset)
__global__ void fill_csr(const void* __restrict__ ei, int E, int n) {
    int e = blockIdx.x * blockDim.x + threadIdx.x;
    if (e < E) {
        int d = load_idx(ei, (long long)E + e);
        int s = load_idx(ei, e);
        if ((unsigned)d < (unsigned)n) {
            int p = atomicAdd(&g_off[d], 1);
            g_col[p] = ((unsigned)s < (unsigned)n) ? s : d;
        }
    }
}

// ---------------- packed fp32 helpers ----------------
__device__ __forceinline__ unsigned long long pack_dup(float x) {
    unsigned long long r;
    asm("mov.b64 %0, {%1, %1};" : "=l"(r) : "f"(x));
    return r;
}
__device__ __forceinline__ void ffma2(unsigned long long& d,
                                      unsigned long long a, unsigned long long b) {
    asm("fma.rn.f32x2 %0, %1, %2, %0;" : "+l"(d) : "l"(a), "l"(b));
}
__device__ __forceinline__ float2 unpack2(unsigned long long v) {
    float2 r;
    asm("mov.b64 {%0, %1}, %2;" : "=f"(r.x), "=f"(r.y) : "l"(v));
    return r;
}

// ---------------- GEMM: Y = op(X) @ W, f32x2 row-pair accumulators ----------------
// 64x64 tile, 256 threads, each thread: 4 rows (2 f32x2 pairs) x 4 cols.
template<int PRE_RELU>
__global__ __launch_bounds__(256) void gemm64(
    const float* __restrict__ X, const float* __restrict__ W,
    const float* __restrict__ scale,     // per-row, may be null
    const float* __restrict__ postBias,  // per-col, may be null
    float* __restrict__ Y, int n)
{
    __shared__ float Xt[64][66];   // Xt[k][r]  (transposed X tile)
    __shared__ float Ws[64][68];   // Ws[k][c]
    int tid  = threadIdx.x;
    int row0 = blockIdx.x * 64;

    #pragma unroll 4
    for (int t = tid; t < 64 * 64; t += 256) {
        int r = t >> 6, c = t & 63;
        Ws[r][c] = W[t];
        int gr = row0 + r;
        float v = (gr < n) ? X[(size_t)gr * 64 + c] : 0.f;
        if (PRE_RELU) v = fmaxf(v, 0.f);
        Xt[c][r] = v;
    }
    __syncthreads();

    int ty = tid >> 4, tx = tid & 15;
    int r0 = ty * 4,  c0 = tx * 4;

    unsigned long long acc[2][4] = {};   // [row-pair][col]

    #pragma unroll
    for (int k = 0; k < 64; k++) {
        unsigned long long xa = *(const unsigned long long*)&Xt[k][r0];      // rows r0,r0+1
        unsigned long long xb = *(const unsigned long long*)&Xt[k][r0 + 2];  // rows r0+2,r0+3
        float4 wv = *(const float4*)&Ws[k][c0];
        unsigned long long w0 = pack_dup(wv.x);
        unsigned long long w1 = pack_dup(wv.y);
        unsigned long long w2 = pack_dup(wv.z);
        unsigned long long w3 = pack_dup(wv.w);
        ffma2(acc[0][0], xa, w0); ffma2(acc[0][1], xa, w1);
        ffma2(acc[0][2], xa, w2); ffma2(acc[0][3], xa, w3);
        ffma2(acc[1][0], xb, w0); ffma2(acc[1][1], xb, w1);
        ffma2(acc[1][2], xb, w2); ffma2(acc[1][3], xb, w3);
    }

    float4 bv = make_float4(0.f, 0.f, 0.f, 0.f);
    if (postBias) bv = *(const float4*)&postBias[c0];

    #pragma unroll
    for (int i = 0; i < 4; i++) {
        int gr = row0 + r0 + i;
        if (gr < n) {
            float s = scale ? scale[gr] : 1.f;
            int p = i >> 1, q = i & 1;
            float2 a0 = unpack2(acc[p][0]);
            float2 a1 = unpack2(acc[p][1]);
            float2 a2 = unpack2(acc[p][2]);
            float2 a3 = unpack2(acc[p][3]);
            float4 o;
            o.x = (q ? a0.y : a0.x) * s + bv.x;
            o.y = (q ? a1.y : a1.x) * s + bv.y;
            o.z = (q ? a2.y : a2.x) * s + bv.z;
            o.w = (q ? a3.y : a3.x) * s + bv.w;
            *(float4*)&Y[(size_t)gr * 64 + c0] = o;
        }
    }
}

// ---------------- Gather aggregation: one warp per node, float2 lanes ----------------
// out[i] = dinv[i] * ( H[i] + sum_{e: dst=i} H[src_e] ) + bias
__global__ __launch_bounds__(256) void gather(
    const float* __restrict__ H, const float* __restrict__ bias,
    float* __restrict__ out, int n)
{
    int warp = (blockIdx.x * blockDim.x + threadIdx.x) >> 5;
    int lane = threadIdx.x & 31;
    if (warp >= n) return;

    int dg = g_deg[warp];
    int o  = g_off[warp] - dg;          // g_off holds end offsets after fill

    float2 a = *(const float2*)(H + (size_t)warp * 64 + lane * 2);   // self loop

    for (int base = 0; base < dg; base += 32) {
        int m  = min(32, dg - base);
        int sj = (lane < m) ? g_col[o + base + lane] : 0;
        #pragma unroll 4
        for (int j = 0; j < m; j++) {
            int s = __shfl_sync(0xffffffffu, sj, j);
            float2 v = *(const float2*)(H + (size_t)s * 64 + lane * 2);
            a.x += v.x;
            a.y += v.y;
        }
    }
    float di = g_dinv[warp];
    float2 bv = *(const float2*)(bias + lane * 2);
    float2 ov;
    ov.x = a.x * di + bv.x;
    ov.y = a.y * di + bv.y;
    *(float2*)(out + (size_t)warp * 64 + lane * 2) = ov;
}

// ---------------- launch ----------------
extern "C" void kernel_launch(void* const* d_in, const int* in_sizes, int n_in,
                              void* d_out, int out_size) {
    const float* x  = (const float*)d_in[0];
    const void*  ei = d_in[1];
    const float* W1 = (const float*)d_in[2];
    const float* b1 = (const float*)d_in[3];
    const float* W2 = (const float*)d_in[4];
    const float* b2 = (const float*)d_in[5];
    const float* Wl = (const float*)d_in[6];
    const float* bl = (const float*)d_in[7];
    float* out = (float*)d_out;

    int n = in_sizes[0] / DIM;          // 100000
    int E = in_sizes[1] / 2;            // 1200000

    float *h, *agg, *dinv;
    cudaGetSymbolAddress((void**)&h,    g_h);
    cudaGetSymbolAddress((void**)&agg,  g_agg);
    cudaGetSymbolAddress((void**)&dinv, g_dinv);

    int nbScan = (n + SCAN_B - 1) / SCAN_B;
    int nbE    = (E + 255) / 256;
    int nbN    = (n + 255) / 256;
    int nbG    = (n * 32 + 255) / 256;       // warp per node
    int nbM    = (n + 63) / 64;

    // CSR build
    init_all<<<nbN, 256>>>((const unsigned int*)ei, n);
    count_deg<<<nbE, 256>>>(ei, E, n);
    scan_lookback<<<nbScan, SCAN_B>>>(n);
    fill_csr<<<nbE, 256>>>(ei, E, n);

    // layer 1
    gemm64<0><<<nbM, 256>>>(x, W1, dinv, nullptr, h, n);
    gather<<<nbG, 256>>>(h, b1, agg, n);

    // layer 2
    gemm64<1><<<nbM, 256>>>(agg, W2, dinv, nullptr, h, n);
    gather<<<nbG, 256>>>(h, b2, agg, n);

    // head
    gemm64<0><<<nbM, 256>>>(agg, Wl, nullptr, bl, out, n);
}